// round 15
// baseline (speedup 1.0000x reference)
#include <cuda_runtime.h>
#include <cuda_fp16.h>
#include <math.h>
#include <stdint.h>

// Problem constants
#define TB 16
#define TS 512
#define TW 5
#define TH 512
#define TE 256
#define TTOK (TB*TS)          // 8192
// Y1 cols: 0..1535 qkv | 1536..1544 gate | 1545..1547 qb | 1548..1663 pad
//          1664..2431 Yp (= X @ (Wq@Bk) + bq@Bk)
#define NY1 2432              // 19 * 128
#define YPOFF 1664
#define NBK 768               // Bk rows (3 types x 256)
#define NU  768               // U cols

typedef __half hf;

// ---------------------------------------------------------------------------
// Scratch (device globals; 16B-aligned)
// ---------------------------------------------------------------------------
__device__ __align__(16) hf g_W1h[(size_t)NY1 * 512];
__device__ __align__(16) hf g_W1l[(size_t)NY1 * 512];
__device__ __align__(16) float g_bbig[NY1];
__device__ __align__(16) hf g_Bkh[NBK * 512];
__device__ __align__(16) hf g_Bkl[NBK * 512];
__device__ __align__(16) hf g_Wq[512 * 512];            // fp16 single
__device__ __align__(16) hf g_Wvh[512 * NU];
__device__ __align__(16) hf g_Wvl[512 * NU];
__device__ __align__(16) hf g_X[(size_t)TTOK * 512];    // fp16 single
__device__ __align__(16) hf g_U[(size_t)TTOK * NU];     // fp16 single
__device__ __align__(16) float g_Y1[(size_t)TTOK * NY1];
__device__ __align__(16) float g_qb[2316];   // [k*3+t] Wq.bkey | [1536+t] bq.bkey | [1548+n] bq.Bk

// ---------------------------------------------------------------------------
// helpers
// ---------------------------------------------------------------------------
__device__ __forceinline__ uint32_t smem_to_u32(const void* p) {
    uint32_t a;
    asm("{ .reg .u64 t; cvta.to.shared.u64 t, %1; cvt.u32.u64 %0, t; }" : "=r"(a) : "l"(p));
    return a;
}
__device__ __forceinline__ void cp_async16(uint32_t dst, const void* src) {
    asm volatile("cp.async.cg.shared.global [%0], [%1], 16;" :: "r"(dst), "l"(src) : "memory");
}
__device__ __forceinline__ void cp_commit() {
    asm volatile("cp.async.commit_group;" ::: "memory");
}
__device__ __forceinline__ void cp_wait1() {
    asm volatile("cp.async.wait_group 1;" ::: "memory");
}
__device__ __forceinline__ void ldmatrix4(uint32_t* r, uint32_t addr) {
    asm volatile("ldmatrix.sync.aligned.m8n8.x4.shared.b16 {%0,%1,%2,%3}, [%4];"
                 : "=r"(r[0]), "=r"(r[1]), "=r"(r[2]), "=r"(r[3]) : "r"(addr));
}
__device__ __forceinline__ void mma16816(float* c, const uint32_t* a, const uint32_t* b) {
    asm volatile("mma.sync.aligned.m16n8k16.row.col.f32.f16.f16.f32 "
                 "{%0,%1,%2,%3}, {%4,%5,%6,%7}, {%8,%9}, {%0,%1,%2,%3};"
                 : "+f"(c[0]), "+f"(c[1]), "+f"(c[2]), "+f"(c[3])
                 : "r"(a[0]), "r"(a[1]), "r"(a[2]), "r"(a[3]), "r"(b[0]), "r"(b[1]));
}
__device__ __forceinline__ void split_store_h(float v, hf* ph, hf* pl) {
    hf h = __float2half_rn(v);
    *ph = h;
    *pl = __float2half_rn(v - __half2float(h));
}

// ---------------------------------------------------------------------------
// fp16 2-term GEMM (R14-proven): C = A @ (Bh+Bl)^T ; 3-stage, single barrier.
// ---------------------------------------------------------------------------
#define G_PART 10240                         // 128*80
#define G_STAGE (3*G_PART)                   // 30720
#define G_SMEM (3*G_STAGE)                   // 92160

template<bool ACCUM, bool BIAS, bool WRITEM>
__global__ __launch_bounds__(256, 2)
void gemm_f16(const hf* __restrict__ A,
              const hf* __restrict__ Bh, const hf* __restrict__ Bl,
              float* __restrict__ C, const float* __restrict__ bias,
              int K, int ldc)
{
    extern __shared__ char smem[];
    const uint32_t smem_base = smem_to_u32(smem);
    const int tid = threadIdx.x;
    const int lane = tid & 31, wid = tid >> 5;
    const int warp_m = wid & 3, warp_n = wid >> 2;
    const int bx = blockIdx.x, by = blockIdx.y;

    const int ld_r = tid >> 1;
    const int ld_c = (tid & 1) * 16;

    const hf* srcA   = A  + (size_t)(by * 128 + ld_r) * K + ld_c;
    const hf* srcB_h = Bh + (size_t)(bx * 128 + ld_r) * K + ld_c;
    const hf* srcB_l = Bl + (size_t)(bx * 128 + ld_r) * K + ld_c;
    const uint32_t dst_base = smem_base + ld_r * 80 + ld_c * 2;

    const int KB = K >> 5;

#define ISSUE_STAGE(kb) do { \
        int _s = (kb) % 3; \
        uint32_t _d = dst_base + _s * G_STAGE; \
        int _k0 = (kb) << 5; \
        cp_async16(_d + 0*G_PART,      srcA + _k0); \
        cp_async16(_d + 0*G_PART + 16, srcA + _k0 + 8); \
        cp_async16(_d + 1*G_PART,      srcB_h + _k0); \
        cp_async16(_d + 1*G_PART + 16, srcB_h + _k0 + 8); \
        cp_async16(_d + 2*G_PART,      srcB_l + _k0); \
        cp_async16(_d + 2*G_PART + 16, srcB_l + _k0 + 8); \
        cp_commit(); \
    } while (0)

    ISSUE_STAGE(0);
    ISSUE_STAGE(1);

    float acc[2][8][4];
#pragma unroll
    for (int i = 0; i < 2; i++)
#pragma unroll
        for (int j = 0; j < 8; j++)
#pragma unroll
            for (int q = 0; q < 4; q++) acc[i][j][q] = 0.f;

    const uint32_t a_row = warp_m * 32 + (lane & 15);
    const uint32_t a_kof = (lane >> 4) * 16;
    const uint32_t b_row = warp_n * 64 + ((lane >> 4) & 1) * 8 + (lane & 7);
    const uint32_t b_kof = ((lane >> 3) & 1) * 16;

    for (int kb = 0; kb < KB; kb++) {
        cp_wait1();                  // stage kb landed (<=1 newer pending)
        __syncthreads();             // everyone done reading stage kb-1
        if (kb + 2 < KB) ISSUE_STAGE(kb + 2);   // overwrites buffer (kb-1)%3
        else cp_commit();

        const uint32_t sb = smem_base + (kb % 3) * G_STAGE;
#pragma unroll
        for (int ks = 0; ks < 2; ks++) {
            uint32_t ah[2][4], bh[8][2], bl[8][2];
            const uint32_t kbyte = ks * 32;
#pragma unroll
            for (int mf = 0; mf < 2; mf++) {
                uint32_t ad = sb + (a_row + mf * 16) * 80 + kbyte + a_kof;
                ldmatrix4(ah[mf], ad + 0 * G_PART);
            }
#pragma unroll
            for (int np = 0; np < 4; np++) {
                uint32_t bd = sb + (b_row + np * 16) * 80 + kbyte + b_kof;
                uint32_t r[4];
                ldmatrix4(r, bd + 1 * G_PART);
                bh[2*np][0] = r[0]; bh[2*np][1] = r[1];
                bh[2*np+1][0] = r[2]; bh[2*np+1][1] = r[3];
                ldmatrix4(r, bd + 2 * G_PART);
                bl[2*np][0] = r[0]; bl[2*np][1] = r[1];
                bl[2*np+1][0] = r[2]; bl[2*np+1][1] = r[3];
            }
#pragma unroll
            for (int mf = 0; mf < 2; mf++)
#pragma unroll
                for (int nf = 0; nf < 8; nf++)
                    mma16816(acc[mf][nf], ah[mf], bh[nf]);
#pragma unroll
            for (int mf = 0; mf < 2; mf++)
#pragma unroll
                for (int nf = 0; nf < 8; nf++)
                    mma16816(acc[mf][nf], ah[mf], bl[nf]);
        }
    }

    // epilogue
    const int row_b = by * 128 + warp_m * 32 + (lane >> 2);
    const int col_b = bx * 128 + warp_n * 64 + (lane & 3) * 2;
#pragma unroll
    for (int mf = 0; mf < 2; mf++) {
#pragma unroll
        for (int nf = 0; nf < 8; nf++) {
            const int row = row_b + mf * 16;
            const int col = col_b + nf * 8;
            float2 v0 = make_float2(acc[mf][nf][0], acc[mf][nf][1]);
            float2 v1 = make_float2(acc[mf][nf][2], acc[mf][nf][3]);
            if (WRITEM) {
                size_t o00 = (size_t)(YPOFF + col)     * 512 + row;
                size_t o10 = (size_t)(YPOFF + col + 1) * 512 + row;
                split_store_h(v0.x, g_W1h + o00, g_W1l + o00);
                split_store_h(v0.y, g_W1h + o10, g_W1l + o10);
                split_store_h(v1.x, g_W1h + o00 + 8, g_W1l + o00 + 8);
                split_store_h(v1.y, g_W1h + o10 + 8, g_W1l + o10 + 8);
                continue;
            }
            if (BIAS) {
                float2 bv = *(const float2*)(bias + col);
                v0.x += bv.x; v0.y += bv.y;
                v1.x += bv.x; v1.y += bv.y;
            }
            float* p0 = C + (size_t)row * ldc + col;
            float* p1 = C + (size_t)(row + 8) * ldc + col;
            if (ACCUM) {
                float2 c0 = *(float2*)p0, c1 = *(float2*)p1;
                v0.x += c0.x; v0.y += c0.y;
                v1.x += c1.x; v1.y += c1.y;
            }
            *(float2*)p0 = v0;
            *(float2*)p1 = v1;
        }
    }
#undef ISSUE_STAGE
}

// ---------------------------------------------------------------------------
// K_qb: warp-per-output fold-in dots (coalesced). fp32.
// ---------------------------------------------------------------------------
__global__ void k_qb(const float* __restrict__ Wh, const float* __restrict__ bh,
                     const float* __restrict__ Wb, const float* __restrict__ bb,
                     const float* __restrict__ Wm, const float* __restrict__ bm,
                     const float* __restrict__ We, const float* __restrict__ be)
{
    int w = (blockIdx.x * blockDim.x + threadIdx.x) >> 5;
    int lane = threadIdx.x & 31;
    if (w >= 2307) return;
    const float* vec;
    const float* other;
    int outi;
    if (w < 1536) {
        int k = w / 3, type = w - k * 3;
        vec = Wh + (size_t)k * 1536;
        other = (type == 0) ? bb : ((type == 1) ? bm : be);
        outi = k * 3 + type;
    } else if (w < 1539) {
        int type = w - 1536;
        vec = bh;
        other = (type == 0) ? bb : ((type == 1) ? bm : be);
        outi = w;
    } else {
        int n = w - 1539;
        int type = n >> 8, e = n & 255;
        const float* W = (type == 0) ? Wb : ((type == 1) ? Wm : We);
        vec = bh;
        other = W + (size_t)e * 1024;
        outi = 1548 + n;
    }
    float s = 0.f;
#pragma unroll
    for (int i = 0; i < 16; i++) {
        int c = lane + i * 32;
        s += vec[c] * other[c];
    }
#pragma unroll
    for (int off = 16; off; off >>= 1) s += __shfl_xor_sync(0xffffffffu, s, off);
    if (lane == 0) g_qb[outi] = s;
}

// ---------------------------------------------------------------------------
// K_prep: coalesced sections only: bias, gate/qb W1 cols, Bk split, Wq, X.
// (W1 qkv cols + Wv handled by k_tw; pad cols 1548..1663 never read -> skipped.)
// ---------------------------------------------------------------------------
__global__ void k_prep(const float* __restrict__ Wh, const float* __restrict__ bh,
                       const float* __restrict__ Wg, const float* __restrict__ bg,
                       const float* __restrict__ Wb, const float* __restrict__ bb,
                       const float* __restrict__ Wm, const float* __restrict__ bm,
                       const float* __restrict__ We, const float* __restrict__ be,
                       const float* __restrict__ X)
{
    int idx = blockIdx.x * blockDim.x + threadIdx.x;
    const int nG  = 12 * 512;     // W1 cols 1536..1547
    const int nBk = NBK * 512;
    const int nWq = 512 * 512;
    const int nX  = TTOK * 512;

    if (idx < NY1) {
        float v = 0.f;
        if (idx < 1536)      v = bh[idx];
        else if (idx < 1545) v = bg[idx - 1536];
        else if (idx < 1548) v = g_qb[1536 + (idx - 1545)];
        else if (idx >= YPOFF) v = g_qb[1548 + (idx - YPOFF)];
        g_bbig[idx] = v;
        return;
    }
    idx -= NY1;
    if (idx < nG) {
        int j = idx / 512, k = idx % 512;        // j = 0..11 -> col 1536+j
        float v = (j < 9) ? Wg[k * 9 + j] : g_qb[k * 3 + (j - 9)];
        size_t o = (size_t)(1536 + j) * 512 + k;
        split_store_h(v, g_W1h + o, g_W1l + o);
        return;
    }
    idx -= nG;
    if (idx < nBk) {
        int n = idx / 512, k = idx % 512;
        int type = n >> 8, e = n & 255;
        const float* W = (type == 0) ? Wb : ((type == 1) ? Wm : We);
        float v = W[e * 1024 + k];               // key half (coalesced in k)
        split_store_h(v, g_Bkh + idx, g_Bkl + idx);
        return;
    }
    idx -= nBk;
    if (idx < nWq) {
        int h = idx / 512, k = idx % 512;
        g_Wq[idx] = __float2half_rn(Wh[(size_t)h * 1536 + k]);   // coalesced in k
        return;
    }
    idx -= nWq;
    if (idx < nX) {
        g_X[idx] = __float2half_rn(X[idx]);
        return;
    }
}

// ---------------------------------------------------------------------------
// K_tw: 32x32 smem-tile transpose + fp16 split (coalesced both directions):
//   blocks 0..767:    W1 qkv cols: g_W1[n][k] = Wh[k][n], n<1536
//   blocks 768..1151: Wv: g_Wv[n][type*256+e] = W_type[e][512+n]
// ---------------------------------------------------------------------------
__global__ __launch_bounds__(256)
void k_tw(const float* __restrict__ Wh,
          const float* __restrict__ Wb, const float* __restrict__ Wm,
          const float* __restrict__ We)
{
    __shared__ float s[32][33];
    const int tid = threadIdx.x;
    const int tx = tid & 31, ty = tid >> 5;   // 32 x 8
    int b = blockIdx.x;

    if (b < 768) {
        int kt = b & 15, nt = b >> 4;         // 16 k-tiles x 48 n-tiles
        int k0 = kt * 32, n0 = nt * 32;
#pragma unroll
        for (int i = 0; i < 4; i++)
            s[ty + i * 8][tx] = Wh[(size_t)(k0 + ty + i * 8) * 1536 + n0 + tx];
        __syncthreads();
#pragma unroll
        for (int i = 0; i < 4; i++) {
            int n = n0 + ty + i * 8;
            int k = k0 + tx;
            size_t o = (size_t)n * 512 + k;
            split_store_h(s[tx][ty + i * 8], g_W1h + o, g_W1l + o);
        }
    } else {
        b -= 768;
        int type = b / 128;
        int bb2 = b - type * 128;
        int et = bb2 & 7, nt = bb2 >> 3;      // 8 e-tiles x 16 n-tiles
        int e0 = et * 32, n0 = nt * 32;
        const float* W = (type == 0) ? Wb : ((type == 1) ? Wm : We);
#pragma unroll
        for (int i = 0; i < 4; i++)
            s[ty + i * 8][tx] = W[(size_t)(e0 + ty + i * 8) * 1024 + 512 + n0 + tx];
        __syncthreads();
#pragma unroll
        for (int i = 0; i < 4; i++) {
            int n = n0 + ty + i * 8;
            int e = e0 + tx;
            size_t o = (size_t)n * NU + type * 256 + e;
            split_store_h(s[tx][ty + i * 8], g_Wvh + o, g_Wvl + o);
        }
    }
}

// ---------------------------------------------------------------------------
// K_mid: 2 tokens per 256-thread block (R9-proven), float4-vectorized loads.
// ---------------------------------------------------------------------------
__device__ __forceinline__ float sigmoidf_(float x) { return 1.f / (1.f + expf(-x)); }

__global__ __launch_bounds__(256)
void k_mid(const int* __restrict__ masks,
           const int* __restrict__ begins, const int* __restrict__ begin_lens,
           const int* __restrict__ middles, const int* __restrict__ middle_lens,
           const int* __restrict__ ends, const int* __restrict__ end_lens,
           const float* __restrict__ emb,
           const float* __restrict__ b_begin, const float* __restrict__ b_middle,
           const float* __restrict__ b_end,
           float* __restrict__ out)
{
    __shared__ float sE[2][15][256];
    __shared__ float sP[2][768];
    __shared__ float sDot[2][16];
    __shared__ float sS[2][16];
    __shared__ float sWgt[2][16];
    __shared__ float sGate[2][3];

    const int tid = threadIdx.x;
    const int half = tid >> 7;
    const int wg = tid & 127;
    const int lane = tid & 31;
    const int warp = tid >> 5;
    const int twarp = warp & 3;
    const int t = blockIdx.x * 2 + half;

    if (wg < 3) {
        int s = t % TS;
        float g;
        if (s == 0 || s == TS - 1) {
            g = (wg == 1) ? 0.f : 1.f;
        } else {
            const float* lm1 = g_Y1 + (size_t)(t - 1) * NY1 + 1536;
            const float* l0  = g_Y1 + (size_t)t * NY1 + 1536;
            const float* lp1 = g_Y1 + (size_t)(t + 1) * NY1 + 1536;
            g = sigmoidf_(lm1[wg] + l0[wg + 3] + lp1[wg + 6]);
        }
        if (masks[t] == 0) g = 0.f;
        sGate[half][wg] = g;
    }

    // stage Yp slice of Y1 row (float4: 192 chunks per token)
    {
        const float4* yp = (const float4*)(g_Y1 + (size_t)t * NY1 + YPOFF);
        float4 v0 = yp[wg];
        *(float4*)(&sP[half][wg * 4]) = v0;
        if (wg < 64) {
            float4 v1 = yp[128 + wg];
            *(float4*)(&sP[half][512 + wg * 4]) = v1;
        }
    }

    // gather 15 emb rows as float4 chunks: 960 chunks per token
    {
        const float4* ef = (const float4*)emb;
#pragma unroll
        for (int i = 0; i < 8; i++) {
            int cid = wg + i * 128;
            if (cid < 960) {
                int r = cid >> 6;
                int c4 = cid & 63;
                int type = r / 5, kk = r - type * 5;
                const int* idxp = (type == 0) ? begins : ((type == 1) ? middles : ends);
                int row = idxp[t * TW + kk];
                float4 v = ef[(size_t)row * 64 + c4];
                *(float4*)(&sE[half][r][c4 * 4]) = v;
            }
        }
    }
    __syncthreads();

    const float* y1 = g_Y1 + (size_t)t * NY1;

    for (int j = twarp; j < 16; j += 4) {
        float sum = 0.f;
        if (j == 0) {
            const float4* yv = (const float4*)y1;
            for (int c = lane; c < 128; c += 32) {
                float4 a = yv[c], b = yv[128 + c];
                sum += a.x * b.x + a.y * b.y + a.z * b.z + a.w * b.w;
            }
        } else {
            int r = j - 1, type = r / 5;
            const float* p = &sP[half][type * 256];
            for (int c = lane; c < 256; c += 32) sum += sE[half][r][c] * p[c];
        }
#pragma unroll
        for (int off = 16; off; off >>= 1) sum += __shfl_xor_sync(0xffffffffu, sum, off);
        if (lane == 0) sDot[half][j] = sum;
    }
    __syncthreads();

    float gts0 = sGate[half][0];
    float gts1 = sGate[half][1];
    float gts2 = sGate[half][2];

    if (wg < 16) {
        float sv;
        if (wg == 0) {
            sv = (masks[t] != 0) ? -1e10f : sDot[half][0];
        } else {
            int r = wg - 1, type = r / 5, k = r % 5;
            int len = ((type == 0) ? begin_lens : ((type == 1) ? middle_lens : end_lens))[t];
            float g = (type == 0) ? gts0 : ((type == 1) ? gts1 : gts2);
            float qb = y1[1545 + type];
            sv = g * (sDot[half][wg] + qb);
            if (k < len) sv = -1e10f;
        }
        sS[half][wg] = sv;
    }
    __syncthreads();

    if (wg < 16) {
        float m = -INFINITY;
#pragma unroll
        for (int i = 0; i < 16; i++) m = fmaxf(m, sS[half][i]);
        sWgt[half][wg] = expf(sS[half][wg] - m);
    }
    __syncthreads();

    float denom = 0.f;
#pragma unroll
    for (int i = 0; i < 16; i++) denom += sWgt[half][i];
    float inv = 1.f / denom;

#pragma unroll
    for (int type = 0; type < 3; type++) {
        float g = (type == 0) ? gts0 : ((type == 1) ? gts1 : gts2);
#pragma unroll
        for (int hcol = 0; hcol < 2; hcol++) {
            int c = wg + hcol * 128;
            float accv = 0.f;
#pragma unroll
            for (int k = 0; k < 5; k++)
                accv += sWgt[half][1 + type * 5 + k] * sE[half][type * 5 + k][c];
            float v = g * inv * accv;
            g_U[(size_t)t * NU + type * 256 + c] = __float2half_rn(v);
        }
    }

    float w0 = sWgt[half][0] * inv;
    float sw[3];
#pragma unroll
    for (int type = 0; type < 3; type++) {
        float g = (type == 0) ? gts0 : ((type == 1) ? gts1 : gts2);
        float ssum = 0.f;
#pragma unroll
        for (int k = 0; k < 5; k++) ssum += sWgt[half][1 + type * 5 + k];
        sw[type] = g * inv * ssum;
    }
    for (int c = wg; c < 512; c += 128) {
        float v = w0 * y1[1024 + c];
        v += sw[0] * b_begin[512 + c] + sw[1] * b_middle[512 + c] + sw[2] * b_end[512 + c];
        out[(size_t)t * 512 + c] = v;
    }
}

// ---------------------------------------------------------------------------
extern "C" void kernel_launch(void* const* d_in, const int* in_sizes, int n_in,
                              void* d_out, int out_size)
{
    const float* hiddens     = (const float*)d_in[0];
    const int*   masks       = (const int*)  d_in[1];
    const int*   begins      = (const int*)  d_in[2];
    const int*   begin_lens  = (const int*)  d_in[3];
    const int*   middles     = (const int*)  d_in[4];
    const int*   middle_lens = (const int*)  d_in[5];
    const int*   ends        = (const int*)  d_in[6];
    const int*   end_lens    = (const int*)  d_in[7];
    const float* emb         = (const float*)d_in[8];
    const float* W_hidden    = (const float*)d_in[9];
    const float* b_hidden    = (const float*)d_in[10];
    const float* W_begin     = (const float*)d_in[11];
    const float* b_begin     = (const float*)d_in[12];
    const float* W_middle    = (const float*)d_in[13];
    const float* b_middle    = (const float*)d_in[14];
    const float* W_end       = (const float*)d_in[15];
    const float* b_end       = (const float*)d_in[16];
    const float* W_gate      = (const float*)d_in[17];
    const float* b_gate      = (const float*)d_in[18];
    float* out = (float*)d_out;

    void *pW1h, *pW1l, *pbbig, *pBkh, *pBkl, *pWq;
    void *pWvh, *pWvl, *pX, *pU, *pY1;
    cudaGetSymbolAddress(&pW1h, g_W1h);  cudaGetSymbolAddress(&pW1l, g_W1l);
    cudaGetSymbolAddress(&pbbig, g_bbig);
    cudaGetSymbolAddress(&pBkh, g_Bkh);  cudaGetSymbolAddress(&pBkl, g_Bkl);
    cudaGetSymbolAddress(&pWq, g_Wq);
    cudaGetSymbolAddress(&pWvh, g_Wvh);  cudaGetSymbolAddress(&pWvl, g_Wvl);
    cudaGetSymbolAddress(&pX, g_X);
    cudaGetSymbolAddress(&pU, g_U);
    cudaGetSymbolAddress(&pY1, g_Y1);

    cudaFuncSetAttribute(gemm_f16<false, true,  false>,
                         cudaFuncAttributeMaxDynamicSharedMemorySize, G_SMEM);
    cudaFuncSetAttribute(gemm_f16<false, false, true>,
                         cudaFuncAttributeMaxDynamicSharedMemorySize, G_SMEM);
    cudaFuncSetAttribute(gemm_f16<true,  false, false>,
                         cudaFuncAttributeMaxDynamicSharedMemorySize, G_SMEM);

    // 0. fold-in dots (warp-per-output, coalesced)
    k_qb<<<(2307 * 32 + 255) / 256, 256>>>(W_hidden, b_hidden,
                                           W_begin, b_begin, W_middle, b_middle,
                                           W_end, b_end);
    // 1a. coalesced prep: bias + gate/qb cols + Bk split + Wq + X
    {
        const int total = NY1 + 12 * 512 + NBK * 512 + 512 * 512 + TTOK * 512;
        k_prep<<<(total + 255) / 256, 256>>>(W_hidden, b_hidden, W_gate, b_gate,
                                             W_begin, b_begin, W_middle, b_middle,
                                             W_end, b_end, hiddens);
    }
    // 1b. transpose-split: W1 qkv cols + Wv
    k_tw<<<1152, 256>>>(W_hidden, W_begin, W_middle, W_end);
    // 2. Wq @ Bk^T -> split-transposed directly into W1 cols 1664..2431 (24 CTAs)
    gemm_f16<false, false, true><<<dim3(NBK / 128, 512 / 128), 256, G_SMEM>>>(
        (const hf*)pWq, (const hf*)pBkh, (const hf*)pBkl,
        nullptr, nullptr, 512, NBK);
    // 3. Y1 = X @ [W_hidden | W_gate | Wq.bkey | pad | Wq@Bk] + bias (19 tiles)
    gemm_f16<false, true, false><<<dim3(NY1 / 128, TTOK / 128), 256, G_SMEM>>>(
        (const hf*)pX, (const hf*)pW1h, (const hf*)pW1l,
        (float*)pY1, (const float*)pbbig, 512, NY1);
    // 4. middle: 2 tokens/block
    k_mid<<<TTOK / 2, 256>>>(masks, begins, begin_lens, middles, middle_lens,
                             ends, end_lens, emb, b_begin, b_middle, b_end, out);
    // 5. out += U @ Wv
    gemm_f16<true, false, false><<<dim3(512 / 128, TTOK / 128), 256, G_SMEM>>>(
        (const hf*)pU, (const hf*)pWvh, (const hf*)pWvl,
        out, nullptr, 768, 512);
}

// round 16
// speedup vs baseline: 1.0157x; 1.0157x over previous
#include <cuda_runtime.h>
#include <cuda_fp16.h>
#include <math.h>
#include <stdint.h>

// Problem constants
#define TB 16
#define TS 512
#define TW 5
#define TH 512
#define TE 256
#define TTOK (TB*TS)          // 8192
// Y1 cols: 0..1535 qkv | 1536..1544 gate | 1545..1547 qb | pad -> 13 tiles
#define NY1 1664
#define NYP 768               // Yp cols (3 types x 256)
#define NBK 768               // Bk rows
#define NU  768               // U cols

typedef __half hf;

// ---------------------------------------------------------------------------
// Scratch (device globals; 16B-aligned)
// ---------------------------------------------------------------------------
__device__ __align__(16) hf g_W1h[(size_t)NY1 * 512];
__device__ __align__(16) hf g_W1l[(size_t)NY1 * 512];
__device__ __align__(16) float g_bbig[NY1];
__device__ __align__(16) hf g_Bkh[NBK * 512];
__device__ __align__(16) hf g_Bkl[NBK * 512];
__device__ __align__(16) hf g_Wvh[512 * NU];
__device__ __align__(16) hf g_Wvl[512 * NU];
__device__ __align__(16) hf g_X[(size_t)TTOK * 512];    // fp16 single
__device__ __align__(16) hf g_Q[(size_t)TTOK * 512];    // fp16 single (GEMM1 epi)
__device__ __align__(16) hf g_U[(size_t)TTOK * NU];     // fp16 single
__device__ __align__(16) float g_Y1[(size_t)TTOK * NY1];
__device__ __align__(16) float g_Yp[(size_t)TTOK * NYP];
__device__ __align__(16) float g_qb[2316];   // [k*3+t] Wq.bkey | [1536+t] bq.bkey | [1548+n] bq.Bk

// ---------------------------------------------------------------------------
// helpers
// ---------------------------------------------------------------------------
__device__ __forceinline__ uint32_t smem_to_u32(const void* p) {
    uint32_t a;
    asm("{ .reg .u64 t; cvta.to.shared.u64 t, %1; cvt.u32.u64 %0, t; }" : "=r"(a) : "l"(p));
    return a;
}
__device__ __forceinline__ void cp_async16(uint32_t dst, const void* src) {
    asm volatile("cp.async.cg.shared.global [%0], [%1], 16;" :: "r"(dst), "l"(src) : "memory");
}
__device__ __forceinline__ void cp_commit() {
    asm volatile("cp.async.commit_group;" ::: "memory");
}
__device__ __forceinline__ void cp_wait1() {
    asm volatile("cp.async.wait_group 1;" ::: "memory");
}
__device__ __forceinline__ void ldmatrix4(uint32_t* r, uint32_t addr) {
    asm volatile("ldmatrix.sync.aligned.m8n8.x4.shared.b16 {%0,%1,%2,%3}, [%4];"
                 : "=r"(r[0]), "=r"(r[1]), "=r"(r[2]), "=r"(r[3]) : "r"(addr));
}
__device__ __forceinline__ void mma16816(float* c, const uint32_t* a, const uint32_t* b) {
    asm volatile("mma.sync.aligned.m16n8k16.row.col.f32.f16.f16.f32 "
                 "{%0,%1,%2,%3}, {%4,%5,%6,%7}, {%8,%9}, {%0,%1,%2,%3};"
                 : "+f"(c[0]), "+f"(c[1]), "+f"(c[2]), "+f"(c[3])
                 : "r"(a[0]), "r"(a[1]), "r"(a[2]), "r"(a[3]), "r"(b[0]), "r"(b[1]));
}
__device__ __forceinline__ void split_store_h(float v, hf* ph, hf* pl) {
    hf h = __float2half_rn(v);
    *ph = h;
    *pl = __float2half_rn(v - __half2float(h));
}

// ---------------------------------------------------------------------------
// fp16 2-term GEMM (R14-proven): C = A @ (Bh+Bl)^T ; 3-stage, single barrier.
// WRITEQ: epilogue also writes cols<512 as single fp16 into g_Q.
// ---------------------------------------------------------------------------
#define G_PART 10240                         // 128*80
#define G_STAGE (3*G_PART)                   // 30720
#define G_SMEM (3*G_STAGE)                   // 92160

template<bool ACCUM, bool BIAS, bool WRITEQ>
__global__ __launch_bounds__(256, 2)
void gemm_f16(const hf* __restrict__ A,
              const hf* __restrict__ Bh, const hf* __restrict__ Bl,
              float* __restrict__ C, const float* __restrict__ bias,
              int K, int ldc)
{
    extern __shared__ char smem[];
    const uint32_t smem_base = smem_to_u32(smem);
    const int tid = threadIdx.x;
    const int lane = tid & 31, wid = tid >> 5;
    const int warp_m = wid & 3, warp_n = wid >> 2;
    const int bx = blockIdx.x, by = blockIdx.y;

    const int ld_r = tid >> 1;
    const int ld_c = (tid & 1) * 16;

    const hf* srcA   = A  + (size_t)(by * 128 + ld_r) * K + ld_c;
    const hf* srcB_h = Bh + (size_t)(bx * 128 + ld_r) * K + ld_c;
    const hf* srcB_l = Bl + (size_t)(bx * 128 + ld_r) * K + ld_c;
    const uint32_t dst_base = smem_base + ld_r * 80 + ld_c * 2;

    const int KB = K >> 5;

#define ISSUE_STAGE(kb) do { \
        int _s = (kb) % 3; \
        uint32_t _d = dst_base + _s * G_STAGE; \
        int _k0 = (kb) << 5; \
        cp_async16(_d + 0*G_PART,      srcA + _k0); \
        cp_async16(_d + 0*G_PART + 16, srcA + _k0 + 8); \
        cp_async16(_d + 1*G_PART,      srcB_h + _k0); \
        cp_async16(_d + 1*G_PART + 16, srcB_h + _k0 + 8); \
        cp_async16(_d + 2*G_PART,      srcB_l + _k0); \
        cp_async16(_d + 2*G_PART + 16, srcB_l + _k0 + 8); \
        cp_commit(); \
    } while (0)

    ISSUE_STAGE(0);
    ISSUE_STAGE(1);

    float acc[2][8][4];
#pragma unroll
    for (int i = 0; i < 2; i++)
#pragma unroll
        for (int j = 0; j < 8; j++)
#pragma unroll
            for (int q = 0; q < 4; q++) acc[i][j][q] = 0.f;

    const uint32_t a_row = warp_m * 32 + (lane & 15);
    const uint32_t a_kof = (lane >> 4) * 16;
    const uint32_t b_row = warp_n * 64 + ((lane >> 4) & 1) * 8 + (lane & 7);
    const uint32_t b_kof = ((lane >> 3) & 1) * 16;

    for (int kb = 0; kb < KB; kb++) {
        cp_wait1();                  // stage kb landed (<=1 newer pending)
        __syncthreads();             // everyone done reading stage kb-1
        if (kb + 2 < KB) ISSUE_STAGE(kb + 2);   // overwrites buffer (kb-1)%3
        else cp_commit();

        const uint32_t sb = smem_base + (kb % 3) * G_STAGE;
#pragma unroll
        for (int ks = 0; ks < 2; ks++) {
            uint32_t ah[2][4], bh[8][2], bl[8][2];
            const uint32_t kbyte = ks * 32;
#pragma unroll
            for (int mf = 0; mf < 2; mf++) {
                uint32_t ad = sb + (a_row + mf * 16) * 80 + kbyte + a_kof;
                ldmatrix4(ah[mf], ad + 0 * G_PART);
            }
#pragma unroll
            for (int np = 0; np < 4; np++) {
                uint32_t bd = sb + (b_row + np * 16) * 80 + kbyte + b_kof;
                uint32_t r[4];
                ldmatrix4(r, bd + 1 * G_PART);
                bh[2*np][0] = r[0]; bh[2*np][1] = r[1];
                bh[2*np+1][0] = r[2]; bh[2*np+1][1] = r[3];
                ldmatrix4(r, bd + 2 * G_PART);
                bl[2*np][0] = r[0]; bl[2*np][1] = r[1];
                bl[2*np+1][0] = r[2]; bl[2*np+1][1] = r[3];
            }
#pragma unroll
            for (int mf = 0; mf < 2; mf++)
#pragma unroll
                for (int nf = 0; nf < 8; nf++)
                    mma16816(acc[mf][nf], ah[mf], bh[nf]);
#pragma unroll
            for (int mf = 0; mf < 2; mf++)
#pragma unroll
                for (int nf = 0; nf < 8; nf++)
                    mma16816(acc[mf][nf], ah[mf], bl[nf]);
        }
    }

    // epilogue
    const int row_b = by * 128 + warp_m * 32 + (lane >> 2);
    const int col_b = bx * 128 + warp_n * 64 + (lane & 3) * 2;
#pragma unroll
    for (int mf = 0; mf < 2; mf++) {
#pragma unroll
        for (int nf = 0; nf < 8; nf++) {
            const int row = row_b + mf * 16;
            const int col = col_b + nf * 8;
            float2 v0 = make_float2(acc[mf][nf][0], acc[mf][nf][1]);
            float2 v1 = make_float2(acc[mf][nf][2], acc[mf][nf][3]);
            if (BIAS) {
                float2 bv = *(const float2*)(bias + col);
                v0.x += bv.x; v0.y += bv.y;
                v1.x += bv.x; v1.y += bv.y;
            }
            float* p0 = C + (size_t)row * ldc + col;
            float* p1 = C + (size_t)(row + 8) * ldc + col;
            if (ACCUM) {
                float2 c0 = *(float2*)p0, c1 = *(float2*)p1;
                v0.x += c0.x; v0.y += c0.y;
                v1.x += c1.x; v1.y += c1.y;
            }
            *(float2*)p0 = v0;
            *(float2*)p1 = v1;
            if (WRITEQ && col < 512) {
                __half2 q0; q0.x = __float2half_rn(v0.x); q0.y = __float2half_rn(v0.y);
                __half2 q1; q1.x = __float2half_rn(v1.x); q1.y = __float2half_rn(v1.y);
                *(__half2*)(g_Q + (size_t)row * 512 + col) = q0;
                *(__half2*)(g_Q + (size_t)(row + 8) * 512 + col) = q1;
            }
        }
    }
#undef ISSUE_STAGE
}

// ---------------------------------------------------------------------------
// K_qb: warp-per-output fold-in dots (coalesced). fp32.
// ---------------------------------------------------------------------------
__global__ void k_qb(const float* __restrict__ Wh, const float* __restrict__ bh,
                     const float* __restrict__ Wb, const float* __restrict__ bb,
                     const float* __restrict__ Wm, const float* __restrict__ bm,
                     const float* __restrict__ We, const float* __restrict__ be)
{
    int w = (blockIdx.x * blockDim.x + threadIdx.x) >> 5;
    int lane = threadIdx.x & 31;
    if (w >= 2307) return;
    const float* vec;
    const float* other;
    int outi;
    if (w < 1536) {
        int k = w / 3, type = w - k * 3;
        vec = Wh + (size_t)k * 1536;
        other = (type == 0) ? bb : ((type == 1) ? bm : be);
        outi = k * 3 + type;
    } else if (w < 1539) {
        int type = w - 1536;
        vec = bh;
        other = (type == 0) ? bb : ((type == 1) ? bm : be);
        outi = w;
    } else {
        int n = w - 1539;
        int type = n >> 8, e = n & 255;
        const float* W = (type == 0) ? Wb : ((type == 1) ? Wm : We);
        vec = bh;
        other = W + (size_t)e * 1024;
        outi = 1548 + n;
    }
    float s = 0.f;
#pragma unroll
    for (int i = 0; i < 16; i++) {
        int c = lane + i * 32;
        s += vec[c] * other[c];
    }
#pragma unroll
    for (int off = 16; off; off >>= 1) s += __shfl_xor_sync(0xffffffffu, s, off);
    if (lane == 0) g_qb[outi] = s;
}

// ---------------------------------------------------------------------------
// K_prep (R14-proven minus Wq): W1 split, bias, Bk split, Wv split, X fp16.
// ---------------------------------------------------------------------------
__global__ void k_prep(const float* __restrict__ Wh, const float* __restrict__ bh,
                       const float* __restrict__ Wg, const float* __restrict__ bg,
                       const float* __restrict__ Wb, const float* __restrict__ bb,
                       const float* __restrict__ Wm, const float* __restrict__ bm,
                       const float* __restrict__ We, const float* __restrict__ be,
                       const float* __restrict__ X)
{
    int idx = blockIdx.x * blockDim.x + threadIdx.x;
    const int nW1 = NY1 * 512;
    const int nBk = NBK * 512;
    const int nWv = 512 * NU;
    const int nX  = TTOK * 512;

    if (idx < nW1) {
        int n = idx / 512, k = idx % 512;
        float v = 0.f;
        if (n < 1536)      v = Wh[k * 1536 + n];
        else if (n < 1545) v = Wg[k * 9 + (n - 1536)];
        else if (n < 1548) v = g_qb[k * 3 + (n - 1545)];
        split_store_h(v, g_W1h + idx, g_W1l + idx);
        return;
    }
    idx -= nW1;
    if (idx < NY1) {
        float v = 0.f;
        if (idx < 1536)      v = bh[idx];
        else if (idx < 1545) v = bg[idx - 1536];
        else if (idx < 1548) v = g_qb[1536 + (idx - 1545)];
        g_bbig[idx] = v;
        return;
    }
    idx -= NY1;
    if (idx < nBk) {
        int n = idx / 512, k = idx % 512;
        int type = n >> 8, e = n & 255;
        const float* W = (type == 0) ? Wb : ((type == 1) ? Wm : We);
        float v = W[e * 1024 + k];               // key half
        split_store_h(v, g_Bkh + idx, g_Bkl + idx);
        return;
    }
    idx -= nBk;
    if (idx < nWv) {
        int n = idx / NU, k = idx % NU;
        int type = k >> 8, e = k & 255;
        const float* W = (type == 0) ? Wb : ((type == 1) ? Wm : We);
        float v = W[e * 1024 + 512 + n];         // value half
        split_store_h(v, g_Wvh + idx, g_Wvl + idx);
        return;
    }
    idx -= nWv;
    if (idx < nX) {
        g_X[idx] = __float2half_rn(X[idx]);
        return;
    }
}

// ---------------------------------------------------------------------------
// K_mid: 2 tokens per 256-thread block (R14-proven; Yp from g_Yp).
// ---------------------------------------------------------------------------
__device__ __forceinline__ float sigmoidf_(float x) { return 1.f / (1.f + expf(-x)); }

__global__ __launch_bounds__(256)
void k_mid(const int* __restrict__ masks,
           const int* __restrict__ begins, const int* __restrict__ begin_lens,
           const int* __restrict__ middles, const int* __restrict__ middle_lens,
           const int* __restrict__ ends, const int* __restrict__ end_lens,
           const float* __restrict__ emb,
           const float* __restrict__ b_begin, const float* __restrict__ b_middle,
           const float* __restrict__ b_end,
           float* __restrict__ out)
{
    __shared__ float sE[2][15][256];
    __shared__ float sP[2][768];
    __shared__ float sDot[2][16];
    __shared__ float sS[2][16];
    __shared__ float sWgt[2][16];
    __shared__ float sGate[2][3];

    const int tid = threadIdx.x;
    const int half = tid >> 7;
    const int wg = tid & 127;
    const int lane = tid & 31;
    const int warp = tid >> 5;
    const int twarp = warp & 3;
    const int t = blockIdx.x * 2 + half;

    if (wg < 3) {
        int s = t % TS;
        float g;
        if (s == 0 || s == TS - 1) {
            g = (wg == 1) ? 0.f : 1.f;
        } else {
            const float* lm1 = g_Y1 + (size_t)(t - 1) * NY1 + 1536;
            const float* l0  = g_Y1 + (size_t)t * NY1 + 1536;
            const float* lp1 = g_Y1 + (size_t)(t + 1) * NY1 + 1536;
            g = sigmoidf_(lm1[wg] + l0[wg + 3] + lp1[wg + 6]);
        }
        if (masks[t] == 0) g = 0.f;
        sGate[half][wg] = g;
    }

    // stage Yp row
    {
        const float* yp = g_Yp + (size_t)t * NYP;
#pragma unroll
        for (int i = 0; i < 3; i++) {
            float2 v = *(const float2*)(yp + i * 256 + wg * 2);
            *(float2*)(&sP[half][i * 256 + wg * 2]) = v;
        }
    }

#pragma unroll
    for (int r = 0; r < 15; r++) {
        int type = r / 5, k = r % 5;
        const int* idxp = (type == 0) ? begins : ((type == 1) ? middles : ends);
        int row = idxp[t * TW + k];
        float2 v = *(const float2*)(emb + (size_t)row * TE + wg * 2);
        *(float2*)(&sE[half][r][wg * 2]) = v;
    }
    __syncthreads();

    const float* y1 = g_Y1 + (size_t)t * NY1;

    for (int j = twarp; j < 16; j += 4) {
        float sum = 0.f;
        if (j == 0) {
            for (int c = lane; c < 512; c += 32) sum += y1[c] * y1[512 + c];
        } else {
            int r = j - 1, type = r / 5;
            const float* p = &sP[half][type * 256];
            for (int c = lane; c < 256; c += 32) sum += sE[half][r][c] * p[c];
        }
#pragma unroll
        for (int off = 16; off; off >>= 1) sum += __shfl_xor_sync(0xffffffffu, sum, off);
        if (lane == 0) sDot[half][j] = sum;
    }
    __syncthreads();

    float gts0 = sGate[half][0];
    float gts1 = sGate[half][1];
    float gts2 = sGate[half][2];

    if (wg < 16) {
        float sv;
        if (wg == 0) {
            sv = (masks[t] != 0) ? -1e10f : sDot[half][0];
        } else {
            int r = wg - 1, type = r / 5, k = r % 5;
            int len = ((type == 0) ? begin_lens : ((type == 1) ? middle_lens : end_lens))[t];
            float g = (type == 0) ? gts0 : ((type == 1) ? gts1 : gts2);
            float qb = y1[1545 + type];
            sv = g * (sDot[half][wg] + qb);
            if (k < len) sv = -1e10f;
        }
        sS[half][wg] = sv;
    }
    __syncthreads();

    if (wg < 16) {
        float m = -INFINITY;
#pragma unroll
        for (int i = 0; i < 16; i++) m = fmaxf(m, sS[half][i]);
        sWgt[half][wg] = expf(sS[half][wg] - m);
    }
    __syncthreads();

    float denom = 0.f;
#pragma unroll
    for (int i = 0; i < 16; i++) denom += sWgt[half][i];
    float inv = 1.f / denom;

#pragma unroll
    for (int type = 0; type < 3; type++) {
        float g = (type == 0) ? gts0 : ((type == 1) ? gts1 : gts2);
#pragma unroll
        for (int hcol = 0; hcol < 2; hcol++) {
            int c = wg + hcol * 128;
            float accv = 0.f;
#pragma unroll
            for (int k = 0; k < 5; k++)
                accv += sWgt[half][1 + type * 5 + k] * sE[half][type * 5 + k][c];
            float v = g * inv * accv;
            g_U[(size_t)t * NU + type * 256 + c] = __float2half_rn(v);
        }
    }

    float w0 = sWgt[half][0] * inv;
    float sw[3];
#pragma unroll
    for (int type = 0; type < 3; type++) {
        float g = (type == 0) ? gts0 : ((type == 1) ? gts1 : gts2);
        float ssum = 0.f;
#pragma unroll
        for (int k = 0; k < 5; k++) ssum += sWgt[half][1 + type * 5 + k];
        sw[type] = g * inv * ssum;
    }
    for (int c = wg; c < 512; c += 128) {
        float v = w0 * y1[1024 + c];
        v += sw[0] * b_begin[512 + c] + sw[1] * b_middle[512 + c] + sw[2] * b_end[512 + c];
        out[(size_t)t * 512 + c] = v;
    }
}

// ---------------------------------------------------------------------------
extern "C" void kernel_launch(void* const* d_in, const int* in_sizes, int n_in,
                              void* d_out, int out_size)
{
    const float* hiddens     = (const float*)d_in[0];
    const int*   masks       = (const int*)  d_in[1];
    const int*   begins      = (const int*)  d_in[2];
    const int*   begin_lens  = (const int*)  d_in[3];
    const int*   middles     = (const int*)  d_in[4];
    const int*   middle_lens = (const int*)  d_in[5];
    const int*   ends        = (const int*)  d_in[6];
    const int*   end_lens    = (const int*)  d_in[7];
    const float* emb         = (const float*)d_in[8];
    const float* W_hidden    = (const float*)d_in[9];
    const float* b_hidden    = (const float*)d_in[10];
    const float* W_begin     = (const float*)d_in[11];
    const float* b_begin     = (const float*)d_in[12];
    const float* W_middle    = (const float*)d_in[13];
    const float* b_middle    = (const float*)d_in[14];
    const float* W_end       = (const float*)d_in[15];
    const float* b_end       = (const float*)d_in[16];
    const float* W_gate      = (const float*)d_in[17];
    const float* b_gate      = (const float*)d_in[18];
    float* out = (float*)d_out;

    void *pW1h, *pW1l, *pbbig, *pBkh, *pBkl;
    void *pWvh, *pWvl, *pX, *pQ, *pU, *pY1, *pYp, *pqb;
    cudaGetSymbolAddress(&pW1h, g_W1h);  cudaGetSymbolAddress(&pW1l, g_W1l);
    cudaGetSymbolAddress(&pbbig, g_bbig);
    cudaGetSymbolAddress(&pBkh, g_Bkh);  cudaGetSymbolAddress(&pBkl, g_Bkl);
    cudaGetSymbolAddress(&pWvh, g_Wvh);  cudaGetSymbolAddress(&pWvl, g_Wvl);
    cudaGetSymbolAddress(&pX, g_X);
    cudaGetSymbolAddress(&pQ, g_Q);
    cudaGetSymbolAddress(&pU, g_U);
    cudaGetSymbolAddress(&pY1, g_Y1);
    cudaGetSymbolAddress(&pYp, g_Yp);
    cudaGetSymbolAddress(&pqb, g_qb);

    cudaFuncSetAttribute(gemm_f16<false, true,  true>,
                         cudaFuncAttributeMaxDynamicSharedMemorySize, G_SMEM);
    cudaFuncSetAttribute(gemm_f16<false, true,  false>,
                         cudaFuncAttributeMaxDynamicSharedMemorySize, G_SMEM);
    cudaFuncSetAttribute(gemm_f16<true,  false, false>,
                         cudaFuncAttributeMaxDynamicSharedMemorySize, G_SMEM);

    // 0. fold-in dots (warp-per-output, coalesced)
    k_qb<<<(2307 * 32 + 255) / 256, 256>>>(W_hidden, b_hidden,
                                           W_begin, b_begin, W_middle, b_middle,
                                           W_end, b_end);
    // 1. prep: W1 split + bias + Bk split + Wv split + X fp16
    {
        const int total = NY1 * 512 + NY1 + NBK * 512 + 512 * NU + TTOK * 512;
        k_prep<<<(total + 255) / 256, 256>>>(W_hidden, b_hidden, W_gate, b_gate,
                                             W_begin, b_begin, W_middle, b_middle,
                                             W_end, b_end, hiddens);
    }
    // 2. Y1 = X @ [W_hidden | W_gate | Wq.bkey] + bias  (13 tiles, writes Q fp16)
    gemm_f16<false, true, true><<<dim3(NY1 / 128, TTOK / 128), 256, G_SMEM>>>(
        (const hf*)pX, (const hf*)pW1h, (const hf*)pW1l,
        (float*)pY1, (const float*)pbbig, 512, NY1);
    // 3. Yp = Q @ Bk + bq@Bk   (6 tiles, 384 CTAs)
    gemm_f16<false, true, false><<<dim3(NYP / 128, TTOK / 128), 256, G_SMEM>>>(
        (const hf*)pQ, (const hf*)pBkh, (const hf*)pBkl,
        (float*)pYp, (const float*)pqb + 1548, 512, NYP);
    // 4. middle: 2 tokens/block
    k_mid<<<TTOK / 2, 256>>>(masks, begins, begin_lens, middles, middle_lens,
                             ends, end_lens, emb, b_begin, b_middle, b_end, out);
    // 5. out += U @ Wv
    gemm_f16<true, false, false><<<dim3(512 / 128, TTOK / 128), 256, G_SMEM>>>(
        (const hf*)pU, (const hf*)pWvh, (const hf*)pWvl,
        out, nullptr, 768, 512);
}